// round 1
// baseline (speedup 1.0000x reference)
#include <cuda_runtime.h>

#define C_CH   256
#define Hf     100
#define Wf     100
#define HWf    (Hf * Wf)
#define GRIDP  8
#define OUTP   7
#define HALF_C 128

// NHWC scratch: [B][H][W][C], B<=2
__device__ float g_featT[2 * HWf * C_CH];

// ---------------------------------------------------------------------------
// Kernel 1: NCHW -> NHWC transpose (per batch, [C=256, HW=10000] -> [HW, C])
// 32x32 smem tiles, coalesced on both sides.
// ---------------------------------------------------------------------------
__global__ void nchw_to_nhwc_kernel(const float* __restrict__ in) {
    __shared__ float tile[32][33];
    const int b   = blockIdx.z;
    const int hw0 = blockIdx.x * 32;
    const int c0  = blockIdx.y * 32;

    const float* inb = in + (size_t)b * C_CH * HWf;
    #pragma unroll
    for (int j = 0; j < 4; ++j) {
        int c  = c0 + threadIdx.y + j * 8;     // always < 256
        int hw = hw0 + threadIdx.x;
        if (hw < HWf)
            tile[threadIdx.y + j * 8][threadIdx.x] = inb[(size_t)c * HWf + hw];
    }
    __syncthreads();

    float* outb = g_featT + (size_t)b * HWf * C_CH;
    #pragma unroll
    for (int j = 0; j < 4; ++j) {
        int hw = hw0 + threadIdx.y + j * 8;
        int c  = c0 + threadIdx.x;
        if (hw < HWf)
            outb[(size_t)hw * C_CH + c] = tile[threadIdx.x][threadIdx.y + j * 8];
    }
}

// ---------------------------------------------------------------------------
// Kernel 2: RoIAlign (8x8 grid, 1 bilinear sample per point) + 2x2/s1 avg pool.
// block = (roi n, channel-half), thread = channel within half.
// Gathers are lane-over-channel on NHWC => 1 cache line per warp request.
// Pooled 7x7 staged in smem (stride 49 = odd => conflict-free), then written
// as a dense float4 stream into the contiguous output chunk.
// ---------------------------------------------------------------------------
__global__ __launch_bounds__(HALF_C) void roi_align_avg_kernel(
    const float* __restrict__ rois,
    const float* __restrict__ scale_p,
    float* __restrict__ out)
{
    __shared__ float s_out[HALF_C * OUTP * OUTP];   // 128*49 floats = 25088 B

    const int n    = blockIdx.x;
    const int half = blockIdx.y;
    const int tid  = threadIdx.x;                   // 0..127
    const int c    = half * HALF_C + tid;           // global channel

    const float scale = scale_p[0];
    const float* r = rois + (size_t)n * 5;
    const int   b  = (int)r[0];
    const float x1 = r[1] * scale;
    const float y1 = r[2] * scale;
    const float x2 = r[3] * scale;
    const float y2 = r[4] * scale;

    const float bw = fmaxf(x2 - x1, 0.0f) / (float)(GRIDP - 1);
    const float bh = fmaxf(y2 - y1, 0.0f) / (float)(GRIDP - 1);

    // Per-column (x) precompute — redundant per thread, trivially cheap.
    int   x0i[GRIDP];
    float lx[GRIDP];
    float vxm[GRIDP];
    #pragma unroll
    for (int g = 0; g < GRIDP; ++g) {
        float xs = x1 + (float)g * bw;
        vxm[g]   = (xs >= 0.0f && xs < (float)Wf) ? 1.0f : 0.0f;
        float xf = fminf(fmaxf(floorf(xs), 0.0f), (float)(Wf - 2));
        x0i[g]   = (int)xf;
        lx[g]    = xs - xf;
    }

    const float* fb = g_featT + (size_t)b * HWf * C_CH + c;

    float prev[GRIDP];
    for (int gy = 0; gy < GRIDP; ++gy) {
        float ys  = y1 + (float)gy * bh;
        float vym = (ys >= 0.0f && ys < (float)Hf) ? 1.0f : 0.0f;
        float yf  = fminf(fmaxf(floorf(ys), 0.0f), (float)(Hf - 2));
        int   y0  = (int)yf;
        float ly  = ys - yf;

        const float* row0 = fb + (size_t)y0 * (Wf * C_CH);

        float cur[GRIDP];
        #pragma unroll
        for (int gx = 0; gx < GRIDP; ++gx) {
            const float* p0 = row0 + x0i[gx] * C_CH;
            float v00 = p0[0];
            float v01 = p0[C_CH];
            float v10 = p0[Wf * C_CH];
            float v11 = p0[Wf * C_CH + C_CH];
            float top = v00 + lx[gx] * (v01 - v00);
            float bot = v10 + lx[gx] * (v11 - v10);
            cur[gx]   = (top + ly * (bot - top)) * (vym * vxm[gx]);
        }

        if (gy > 0) {
            #pragma unroll
            for (int ox = 0; ox < OUTP; ++ox)
                s_out[tid * (OUTP * OUTP) + (gy - 1) * OUTP + ox] =
                    0.25f * (prev[ox] + prev[ox + 1] + cur[ox] + cur[ox + 1]);
        }
        #pragma unroll
        for (int i = 0; i < GRIDP; ++i) prev[i] = cur[i];
    }

    __syncthreads();

    // Dense coalesced write of this block's contiguous output chunk:
    // out[n][half*128 .. half*128+127][0..6][0..6]  = 6272 floats = 1568 float4
    float4*       o4 = (float4*)(out + (size_t)n * (C_CH * OUTP * OUTP)
                                      + (size_t)half * (HALF_C * OUTP * OUTP));
    const float4* s4 = (const float4*)s_out;
    const int n4 = (HALF_C * OUTP * OUTP) / 4;     // 1568
    for (int i = tid; i < n4; i += HALF_C)
        o4[i] = s4[i];
}

extern "C" void kernel_launch(void* const* d_in, const int* in_sizes, int n_in,
                              void* d_out, int out_size) {
    const float* feat  = (const float*)d_in[0];
    const float* rois  = (const float*)d_in[1];
    const float* scale = (const float*)d_in[2];
    float*       out   = (float*)d_out;

    const int B = in_sizes[0] / (C_CH * HWf);   // 2
    const int N = in_sizes[1] / 5;              // 2048

    // 1) NCHW -> NHWC into device scratch
    dim3 tb(32, 8);
    dim3 tg((HWf + 31) / 32, C_CH / 32, B);
    nchw_to_nhwc_kernel<<<tg, tb>>>(feat);

    // 2) RoIAlign + avg-pool
    dim3 rg(N, C_CH / HALF_C);
    roi_align_avg_kernel<<<rg, HALF_C>>>(rois, scale, out);
}